// round 2
// baseline (speedup 1.0000x reference)
#include <cuda_runtime.h>
#include <math.h>
#include <stdint.h>

#define D_MODEL 1024
#define N_HEADS 16
#define HEAD_DIM 64
#define SEQ_L 2048
#define BATCH 2
#define M_TOTAL (BATCH * SEQ_L)   // 4096

#define BM 128
#define BN 128
#define BK 16

// ---------------- scratch (static device globals; no allocation) -------------
__device__ float g_q[M_TOTAL * D_MODEL];
__device__ float g_k[M_TOTAL * D_MODEL];
__device__ float g_v[M_TOTAL * D_MODEL];
__device__ float g_attn[M_TOTAL * D_MODEL];
__device__ int   g_ridx[SEQ_L * 2];

// ---------------- Threefry-2x32 (JAX-compatible) -----------------------------
__device__ __forceinline__ unsigned rotl32(unsigned x, int d) {
    return (x << d) | (x >> (32 - d));
}

__device__ void threefry2x32(unsigned k0, unsigned k1, unsigned c0, unsigned c1,
                             unsigned& o0, unsigned& o1) {
    unsigned k2 = k0 ^ k1 ^ 0x1BD11BDAu;
    unsigned x0 = c0 + k0, x1 = c1 + k1;
#define TF_RND(r) { x0 += x1; x1 = rotl32(x1, (r)); x1 ^= x0; }
    TF_RND(13) TF_RND(15) TF_RND(26) TF_RND(6)
    x0 += k1; x1 += k2 + 1u;
    TF_RND(17) TF_RND(29) TF_RND(16) TF_RND(24)
    x0 += k2; x1 += k0 + 2u;
    TF_RND(13) TF_RND(15) TF_RND(26) TF_RND(6)
    x0 += k0; x1 += k1 + 3u;
    TF_RND(17) TF_RND(29) TF_RND(16) TF_RND(24)
    x0 += k1; x1 += k2 + 4u;
    TF_RND(13) TF_RND(15) TF_RND(26) TF_RND(6)
    x0 += k2; x1 += k0 + 5u;
#undef TF_RND
    o0 = x0; o1 = x1;
}

// Reproduce jax.random.uniform(key(42), (2048, 2)) under the MODERN JAX default
// jax_threefry_partitionable=True: counter-mode, per element n (uint64 counter),
// bits32[n] = o0 ^ o1 of threefry2x32(key=(0,42), counter=(hi(n)=0, lo(n)=n)).
// Then ridx[i,c] = floor(u * (i+1)) with u = bitcast((bits>>9)|0x3f800000) - 1.
__global__ void ridx_kernel() {
    int i = blockIdx.x * blockDim.x + threadIdx.x;
    if (i >= SEQ_L) return;
#pragma unroll
    for (int c = 0; c < 2; ++c) {
        unsigned n = (unsigned)(2 * i + c);   // counter < 2^32 -> hi = 0
        unsigned o0, o1;
        threefry2x32(0u, 42u, 0u, n, o0, o1);
        unsigned bits = o0 ^ o1;
        float u = __uint_as_float((bits >> 9) | 0x3f800000u) - 1.0f;
        g_ridx[2 * i + c] = (int)(u * (float)(i + 1));
    }
}

// ---------------- SGEMM: C[M,N] = A[M,K] * W[N,K]^T (all row-major) ----------
// Fixed: N = K = 1024; grid = (N/BN, M/BM); 256 threads; 8x8 per-thread tile.
__global__ __launch_bounds__(256) void sgemm_nt_kernel(
    const float* __restrict__ A, const float* __restrict__ W,
    float* __restrict__ C) {
    const int K = 1024, N = 1024;
    __shared__ float As[BK][BM];
    __shared__ float Ws[BK][BN];

    int tid = threadIdx.x;
    int tx = tid & 15;          // 0..15 (N micro-tiles)
    int ty = tid >> 4;          // 0..15 (M micro-tiles)
    int r  = tid >> 2;          // 0..63 (load row)
    int cq = (tid & 3) * 4;     // 0,4,8,12 (k offset, float4)

    const float* Ab = A + (size_t)blockIdx.y * BM * K;
    const float* Wb = W + (size_t)blockIdx.x * BN * K;

    float acc[8][8];
#pragma unroll
    for (int i = 0; i < 8; ++i)
#pragma unroll
        for (int j = 0; j < 8; ++j) acc[i][j] = 0.f;

    for (int kt = 0; kt < K; kt += BK) {
        float4 a0 = *(const float4*)(Ab + (size_t)r * K + kt + cq);
        float4 a1 = *(const float4*)(Ab + (size_t)(r + 64) * K + kt + cq);
        float4 w0 = *(const float4*)(Wb + (size_t)r * K + kt + cq);
        float4 w1 = *(const float4*)(Wb + (size_t)(r + 64) * K + kt + cq);

        As[cq + 0][r] = a0.x; As[cq + 1][r] = a0.y; As[cq + 2][r] = a0.z; As[cq + 3][r] = a0.w;
        As[cq + 0][r + 64] = a1.x; As[cq + 1][r + 64] = a1.y; As[cq + 2][r + 64] = a1.z; As[cq + 3][r + 64] = a1.w;
        Ws[cq + 0][r] = w0.x; Ws[cq + 1][r] = w0.y; Ws[cq + 2][r] = w0.z; Ws[cq + 3][r] = w0.w;
        Ws[cq + 0][r + 64] = w1.x; Ws[cq + 1][r + 64] = w1.y; Ws[cq + 2][r + 64] = w1.z; Ws[cq + 3][r + 64] = w1.w;
        __syncthreads();

#pragma unroll
        for (int kk = 0; kk < BK; ++kk) {
            float4 ra0 = *(const float4*)&As[kk][ty * 8];
            float4 ra1 = *(const float4*)&As[kk][ty * 8 + 4];
            float4 rb0 = *(const float4*)&Ws[kk][tx * 8];
            float4 rb1 = *(const float4*)&Ws[kk][tx * 8 + 4];
            float ra[8] = {ra0.x, ra0.y, ra0.z, ra0.w, ra1.x, ra1.y, ra1.z, ra1.w};
            float rb[8] = {rb0.x, rb0.y, rb0.z, rb0.w, rb1.x, rb1.y, rb1.z, rb1.w};
#pragma unroll
            for (int i = 0; i < 8; ++i)
#pragma unroll
                for (int j = 0; j < 8; ++j)
                    acc[i][j] = fmaf(ra[i], rb[j], acc[i][j]);
        }
        __syncthreads();
    }

    float* Cb = C + ((size_t)blockIdx.y * BM + ty * 8) * N + blockIdx.x * BN + tx * 8;
#pragma unroll
    for (int i = 0; i < 8; ++i) {
        *(float4*)(Cb + (size_t)i * N)     = make_float4(acc[i][0], acc[i][1], acc[i][2], acc[i][3]);
        *(float4*)(Cb + (size_t)i * N + 4) = make_float4(acc[i][4], acc[i][5], acc[i][6], acc[i][7]);
    }
}

// ---------------- RoPE (in-place on g_q, g_k) --------------------------------
// one thread per (b, t, h, pair j); total = 2*2048*16*32 = 2097152 = 8192*256
__global__ __launch_bounds__(256) void rope_kernel(const float* __restrict__ freqs) {
    int idx = blockIdx.x * 256 + threadIdx.x;
    int j = idx & 31;
    int h = (idx >> 5) & 15;
    int t = (idx >> 9) & (SEQ_L - 1);
    int b = idx >> 20;
    float ang = freqs[t * 32 + j];
    float sn, cs;
    sincosf(ang, &sn, &cs);
    size_t base = ((size_t)(b * SEQ_L + t)) * D_MODEL + h * HEAD_DIM + 2 * j;
    float2 qp = *(float2*)(g_q + base);
    *(float2*)(g_q + base) = make_float2(qp.x * cs - qp.y * sn, qp.x * sn + qp.y * cs);
    float2 kp = *(float2*)(g_k + base);
    *(float2*)(g_k + base) = make_float2(kp.x * cs - kp.y * sn, kp.x * sn + kp.y * cs);
}

// ---------------- Sparse BigBird attention -----------------------------------
// one warp per (b, h, i); warps with consecutive i adjacent for K/V L2 reuse.
__global__ __launch_bounds__(256) void attn_kernel() {
    int gtid = blockIdx.x * 256 + threadIdx.x;
    int w = gtid >> 5;
    int lane = gtid & 31;
    int i = w & (SEQ_L - 1);
    int bh = w >> 11;
    int h = bh & (N_HEADS - 1);
    int b = bh >> 4;

    size_t rowq = ((size_t)(b * SEQ_L + i)) * D_MODEL + h * HEAD_DIM;
    float2 qv = *(const float2*)(g_q + rowq + 2 * lane);
    size_t kvbase = ((size_t)b * SEQ_L) * D_MODEL + h * HEAD_DIM + 2 * lane;
    const float scale = 0.125f;   // 1/sqrt(64)
    float ax, ay;

    if (i == 0) {
        // global row: attends to ALL columns (non-causal), online softmax
        float mx = -1e30f, den = 0.f;
        ax = ay = 0.f;
        for (int j = 0; j < SEQ_L; ++j) {
            float2 kv = *(const float2*)(g_k + kvbase + (size_t)j * D_MODEL);
            float d = qv.x * kv.x + qv.y * kv.y;
#pragma unroll
            for (int off = 16; off; off >>= 1) d += __shfl_xor_sync(0xffffffffu, d, off);
            float s = d * scale;
            float nm = fmaxf(mx, s);
            float corr = expf(mx - nm);
            float wgt = expf(s - nm);
            float2 vv = *(const float2*)(g_v + kvbase + (size_t)j * D_MODEL);
            den = den * corr + wgt;
            ax = ax * corr + wgt * vv.x;
            ay = ay * corr + wgt * vv.y;
            mx = nm;
        }
        float inv = 1.f / den;
        ax *= inv; ay *= inv;
    } else {
        int r0 = g_ridx[2 * i], r1 = g_ridx[2 * i + 1];
        float p[11];
        int js[11];
        unsigned vm = 0;
#pragma unroll
        for (int s = 0; s < 11; ++s) {
            int j; bool valid;
            if (s == 0)      { j = 0; valid = true; }
            else if (s <= 8) { j = i - 8 + s; valid = (j >= 1); }
            else {
                j = (s == 9) ? r0 : r1;
                valid = (j >= 1) && (j <= i - 8) && ((s == 9) || (j != r0));
            }
            float sv = -1e30f;
            if (valid) {
                float2 kv = *(const float2*)(g_k + kvbase + (size_t)j * D_MODEL);
                float d = qv.x * kv.x + qv.y * kv.y;
#pragma unroll
                for (int off = 16; off; off >>= 1) d += __shfl_xor_sync(0xffffffffu, d, off);
                sv = d * scale;
                vm |= 1u << s;
            }
            p[s] = sv;
            js[s] = j;
        }
        float mx = p[0];
#pragma unroll
        for (int s = 1; s < 11; ++s) mx = fmaxf(mx, p[s]);
        float den = 0.f;
#pragma unroll
        for (int s = 0; s < 11; ++s) {
            p[s] = ((vm >> s) & 1u) ? expf(p[s] - mx) : 0.f;
            den += p[s];
        }
        float inv = 1.f / den;
        ax = ay = 0.f;
#pragma unroll
        for (int s = 0; s < 11; ++s) {
            if ((vm >> s) & 1u) {
                float2 vv = *(const float2*)(g_v + kvbase + (size_t)js[s] * D_MODEL);
                ax += p[s] * vv.x;
                ay += p[s] * vv.y;
            }
        }
        ax *= inv; ay *= inv;
    }
    *(float2*)(g_attn + rowq + 2 * lane) = make_float2(ax, ay);
}

// ---------------- launch ------------------------------------------------------
extern "C" void kernel_launch(void* const* d_in, const int* in_sizes, int n_in,
                              void* d_out, int out_size) {
    const float* x     = (const float*)d_in[0];
    const float* freqs = (const float*)d_in[1];
    const float* wq    = (const float*)d_in[2];
    const float* wk    = (const float*)d_in[3];
    const float* wv    = (const float*)d_in[4];
    const float* wo    = (const float*)d_in[5];
    float* out = (float*)d_out;

    float *qp, *kp, *vp, *ap;
    cudaGetSymbolAddress((void**)&qp, g_q);
    cudaGetSymbolAddress((void**)&kp, g_k);
    cudaGetSymbolAddress((void**)&vp, g_v);
    cudaGetSymbolAddress((void**)&ap, g_attn);

    dim3 gg(1024 / BN, M_TOTAL / BM);   // (8, 32)
    sgemm_nt_kernel<<<gg, 256>>>(x, wq, qp);
    sgemm_nt_kernel<<<gg, 256>>>(x, wk, kp);
    sgemm_nt_kernel<<<gg, 256>>>(x, wv, vp);
    rope_kernel<<<8192, 256>>>(freqs);
    ridx_kernel<<<8, 256>>>();
    attn_kernel<<<8192, 256>>>();
    sgemm_nt_kernel<<<gg, 256>>>(ap, wo, out);
}

// round 4
// speedup vs baseline: 1.4223x; 1.4223x over previous
#include <cuda_runtime.h>
#include <cuda_bf16.h>
#include <math.h>
#include <stdint.h>

#define D_MODEL 1024
#define N_HEADS 16
#define HEAD_DIM 64
#define SEQ_L 2048
#define BATCH 2
#define M_TOTAL (BATCH * SEQ_L)   // 4096

// ---------------- scratch (static device globals; no allocation) -------------
__device__ __align__(256) float g_q[M_TOTAL * D_MODEL];
__device__ __align__(256) float g_k[M_TOTAL * D_MODEL];
__device__ __align__(256) float g_v[M_TOTAL * D_MODEL];
__device__ __align__(256) float g_attn[M_TOTAL * D_MODEL];
__device__ int g_ridx[SEQ_L * 2];

__device__ __align__(256) __nv_bfloat16 g_xhi[M_TOTAL * D_MODEL];
__device__ __align__(256) __nv_bfloat16 g_xlo[M_TOTAL * D_MODEL];
__device__ __align__(256) __nv_bfloat16 g_ahi[M_TOTAL * D_MODEL];
__device__ __align__(256) __nv_bfloat16 g_alo[M_TOTAL * D_MODEL];
__device__ __align__(256) __nv_bfloat16 g_whi[4][D_MODEL * D_MODEL];
__device__ __align__(256) __nv_bfloat16 g_wlo[4][D_MODEL * D_MODEL];

// ---------------- baseline-ISA helpers ---------------------------------------
__device__ __forceinline__ uint32_t smem_to_u32(const void* p) {
    uint32_t a;
    asm("{ .reg .u64 t; cvta.to.shared.u64 t, %1; cvt.u32.u64 %0, t; }" : "=r"(a) : "l"(p));
    return a;
}
__device__ __forceinline__ void cp16(uint32_t s, const void* g) {
    asm volatile("cp.async.cg.shared.global [%0], [%1], 16;" :: "r"(s), "l"(g) : "memory");
}
#define CP_COMMIT() asm volatile("cp.async.commit_group;" ::: "memory")
#define CP_WAIT0()  asm volatile("cp.async.wait_group 0;" ::: "memory")

__device__ __forceinline__ void ldm4(uint32_t (&r)[4], uint32_t addr) {
    asm volatile("ldmatrix.sync.aligned.m8n8.x4.shared.b16 {%0,%1,%2,%3}, [%4];"
                 : "=r"(r[0]), "=r"(r[1]), "=r"(r[2]), "=r"(r[3]) : "r"(addr));
}
__device__ __forceinline__ void mma16816(float (&d)[4], const uint32_t (&a)[4],
                                         uint32_t b0, uint32_t b1) {
    asm volatile(
        "mma.sync.aligned.m16n8k16.row.col.f32.bf16.bf16.f32 "
        "{%0,%1,%2,%3}, {%4,%5,%6,%7}, {%8,%9}, {%0,%1,%2,%3};"
        : "+f"(d[0]), "+f"(d[1]), "+f"(d[2]), "+f"(d[3])
        : "r"(a[0]), "r"(a[1]), "r"(a[2]), "r"(a[3]), "r"(b0), "r"(b1));
}

// ---------------- Threefry-2x32 (JAX partitionable) --------------------------
__device__ __forceinline__ unsigned rotl32(unsigned x, int d) {
    return (x << d) | (x >> (32 - d));
}
__device__ void threefry2x32(unsigned k0, unsigned k1, unsigned c0, unsigned c1,
                             unsigned& o0, unsigned& o1) {
    unsigned k2 = k0 ^ k1 ^ 0x1BD11BDAu;
    unsigned x0 = c0 + k0, x1 = c1 + k1;
#define TF_RND(r) { x0 += x1; x1 = rotl32(x1, (r)); x1 ^= x0; }
    TF_RND(13) TF_RND(15) TF_RND(26) TF_RND(6)
    x0 += k1; x1 += k2 + 1u;
    TF_RND(17) TF_RND(29) TF_RND(16) TF_RND(24)
    x0 += k2; x1 += k0 + 2u;
    TF_RND(13) TF_RND(15) TF_RND(26) TF_RND(6)
    x0 += k0; x1 += k1 + 3u;
    TF_RND(17) TF_RND(29) TF_RND(16) TF_RND(24)
    x0 += k1; x1 += k2 + 4u;
    TF_RND(13) TF_RND(15) TF_RND(26) TF_RND(6)
    x0 += k2; x1 += k0 + 5u;
#undef TF_RND
    o0 = x0; o1 = x1;
}
__global__ void ridx_kernel() {
    int i = blockIdx.x * blockDim.x + threadIdx.x;
    if (i >= SEQ_L) return;
#pragma unroll
    for (int c = 0; c < 2; ++c) {
        unsigned n = (unsigned)(2 * i + c);
        unsigned o0, o1;
        threefry2x32(0u, 42u, 0u, n, o0, o1);
        unsigned bits = o0 ^ o1;
        float u = __uint_as_float((bits >> 9) | 0x3f800000u) - 1.0f;
        g_ridx[2 * i + c] = (int)(u * (float)(i + 1));
    }
}

// ---------------- fp32 -> bf16 hi/lo split ------------------------------------
__global__ __launch_bounds__(256) void split_kernel(const float* __restrict__ src,
                                                    __nv_bfloat16* __restrict__ hi,
                                                    __nv_bfloat16* __restrict__ lo, int n) {
    int i = blockIdx.x * 256 + threadIdx.x;
    if (i < n) {
        float v = src[i];
        __nv_bfloat16 h = __float2bfloat16(v);
        hi[i] = h;
        lo[i] = __float2bfloat16(v - __bfloat162float(h));
    }
}

// ---------------- HMMA GEMM: C[M,1024] = A[M,1024] * B[1024,1024]^T ----------
// 3-term compensated bf16: C = Ahi*Bhi + Alo*Bhi + Ahi*Blo (96 K-iters of 32).
// CTA tile 128x128x32, 256 thr, warps 4(M) x 2(N), warp tile 32x64 (m16n8k16).
// smem: double-buffered A/B tiles, 64B rows, XOR-4 chunk swizzle.
__global__ __launch_bounds__(256, 2) void gemm_hmma3_kernel(
    const __nv_bfloat16* __restrict__ Ahi, const __nv_bfloat16* __restrict__ Alo,
    const __nv_bfloat16* __restrict__ Bhi, const __nv_bfloat16* __restrict__ Blo,
    float* __restrict__ C) {
    __shared__ __align__(128) char smA[2][8192];
    __shared__ __align__(128) char smB[2][8192];

    const int tid = threadIdx.x;
    const int lane = tid & 31;
    const int wid = tid >> 5;
    const int wm = wid >> 1;          // 0..3
    const int wn = wid & 1;           // 0..1
    const int Mbase = blockIdx.y * 128;
    const int Nbase = blockIdx.x * 128;

    const __nv_bfloat16* Asrc[3] = {Ahi, Alo, Ahi};
    const __nv_bfloat16* Bsrc[3] = {Bhi, Bhi, Blo};

    // per-thread load indices (2 chunks per tensor per stage)
    const int r0 = tid >> 2, c0 = tid & 3;
    const int r1 = (tid + 256) >> 2, c1 = (tid + 256) & 3;
    const uint32_t swo0 = (uint32_t)(r0 * 64 + ((c0 ^ (r0 & 3)) << 4));
    const uint32_t swo1 = (uint32_t)(r1 * 64 + ((c1 ^ (r1 & 3)) << 4));
    uint32_t sA[2] = {smem_to_u32(smA[0]), smem_to_u32(smA[1])};
    uint32_t sB[2] = {smem_to_u32(smB[0]), smem_to_u32(smB[1])};

    float acc[2][8][4];
#pragma unroll
    for (int mt = 0; mt < 2; ++mt)
#pragma unroll
        for (int np = 0; np < 8; ++np)
#pragma unroll
            for (int e = 0; e < 4; ++e) acc[mt][np][e] = 0.f;

    // ldmatrix lane-address components (fixed per thread)
    // A: row = wm*32 + mt*16 + (lane & 15); chunk = ks*2 + (lane >> 4)
    const int arow_l = (lane & 15);
    const int achk_l = (lane >> 4);
    // B: row = wn*64 + p*16 + (lane & 7) + ((lane >> 4) << 3); chunk = ks*2 + ((lane >> 3) & 1)
    const int brow_l = (lane & 7) + ((lane >> 4) << 3);
    const int bchk_l = ((lane >> 3) & 1);

    // prologue: stage 0
    {
        const __nv_bfloat16* A = Asrc[0];
        const __nv_bfloat16* B = Bsrc[0];
        cp16(sA[0] + swo0, A + (size_t)(Mbase + r0) * 1024 + c0 * 8);
        cp16(sA[0] + swo1, A + (size_t)(Mbase + r1) * 1024 + c1 * 8);
        cp16(sB[0] + swo0, B + (size_t)(Nbase + r0) * 1024 + c0 * 8);
        cp16(sB[0] + swo1, B + (size_t)(Nbase + r1) * 1024 + c1 * 8);
        CP_COMMIT();
    }

    for (int g = 0; g < 96; ++g) {
        const int buf = g & 1;
        CP_WAIT0();
        __syncthreads();

        if (g + 1 < 96) {
            const int gn = g + 1;
            const int term = gn >> 5, kt = gn & 31;
            const __nv_bfloat16* A = Asrc[term];
            const __nv_bfloat16* B = Bsrc[term];
            const int ko = kt * 32;
            cp16(sA[buf ^ 1] + swo0, A + (size_t)(Mbase + r0) * 1024 + ko + c0 * 8);
            cp16(sA[buf ^ 1] + swo1, A + (size_t)(Mbase + r1) * 1024 + ko + c1 * 8);
            cp16(sB[buf ^ 1] + swo0, B + (size_t)(Nbase + r0) * 1024 + ko + c0 * 8);
            cp16(sB[buf ^ 1] + swo1, B + (size_t)(Nbase + r1) * 1024 + ko + c1 * 8);
            CP_COMMIT();
        }

#pragma unroll
        for (int ks = 0; ks < 2; ++ks) {
            uint32_t afr[2][4];
#pragma unroll
            for (int mt = 0; mt < 2; ++mt) {
                int r = wm * 32 + mt * 16 + arow_l;
                int c = ks * 2 + achk_l;
                ldm4(afr[mt], sA[buf] + (uint32_t)(r * 64 + ((c ^ (r & 3)) << 4)));
            }
            uint32_t bfr[4][4];
#pragma unroll
            for (int p = 0; p < 4; ++p) {
                int r = wn * 64 + p * 16 + brow_l;
                int c = ks * 2 + bchk_l;
                ldm4(bfr[p], sB[buf] + (uint32_t)(r * 64 + ((c ^ (r & 3)) << 4)));
            }
#pragma unroll
            for (int mt = 0; mt < 2; ++mt)
#pragma unroll
                for (int p = 0; p < 4; ++p) {
                    mma16816(acc[mt][2 * p],     afr[mt], bfr[p][0], bfr[p][1]);
                    mma16816(acc[mt][2 * p + 1], afr[mt], bfr[p][2], bfr[p][3]);
                }
        }
        __syncthreads();
    }

    // epilogue: c0,c1 -> (m = lane/4, n = (lane%4)*2), c2,c3 -> m+8
#pragma unroll
    for (int mt = 0; mt < 2; ++mt) {
        int mr = Mbase + wm * 32 + mt * 16 + (lane >> 2);
#pragma unroll
        for (int np = 0; np < 8; ++np) {
            int nc = Nbase + wn * 64 + np * 8 + (lane & 3) * 2;
            float* p0 = C + (size_t)mr * 1024 + nc;
            p0[0] = acc[mt][np][0];
            p0[1] = acc[mt][np][1];
            float* p1 = p0 + 8 * 1024;
            p1[0] = acc[mt][np][2];
            p1[1] = acc[mt][np][3];
        }
    }
}

// ---------------- RoPE (in-place on g_q, g_k) --------------------------------
__global__ __launch_bounds__(256) void rope_kernel(const float* __restrict__ freqs) {
    int idx = blockIdx.x * 256 + threadIdx.x;
    int j = idx & 31;
    int h = (idx >> 5) & 15;
    int t = (idx >> 9) & (SEQ_L - 1);
    int b = idx >> 20;
    float ang = freqs[t * 32 + j];
    float sn, cs;
    sincosf(ang, &sn, &cs);
    size_t base = ((size_t)(b * SEQ_L + t)) * D_MODEL + h * HEAD_DIM + 2 * j;
    float2 qp = *(float2*)(g_q + base);
    *(float2*)(g_q + base) = make_float2(qp.x * cs - qp.y * sn, qp.x * sn + qp.y * cs);
    float2 kp = *(float2*)(g_k + base);
    *(float2*)(g_k + base) = make_float2(kp.x * cs - kp.y * sn, kp.x * sn + kp.y * cs);
}

// ---------------- Sparse BigBird attention -----------------------------------
__global__ __launch_bounds__(256) void attn_kernel() {
    int gtid = blockIdx.x * 256 + threadIdx.x;
    int w = gtid >> 5;
    int lane = gtid & 31;
    int i = w & (SEQ_L - 1);
    int bh = w >> 11;
    int h = bh & (N_HEADS - 1);
    int b = bh >> 4;

    size_t rowq = ((size_t)(b * SEQ_L + i)) * D_MODEL + h * HEAD_DIM;
    float2 qv = *(const float2*)(g_q + rowq + 2 * lane);
    size_t kvbase = ((size_t)b * SEQ_L) * D_MODEL + h * HEAD_DIM + 2 * lane;
    const float scale = 0.125f;
    float ax, ay;

    if (i == 0) {
        float mx = -1e30f, den = 0.f;
        ax = ay = 0.f;
        for (int j = 0; j < SEQ_L; ++j) {
            float2 kv = *(const float2*)(g_k + kvbase + (size_t)j * D_MODEL);
            float d = qv.x * kv.x + qv.y * kv.y;
#pragma unroll
            for (int off = 16; off; off >>= 1) d += __shfl_xor_sync(0xffffffffu, d, off);
            float s = d * scale;
            float nm = fmaxf(mx, s);
            float corr = expf(mx - nm);
            float wgt = expf(s - nm);
            float2 vv = *(const float2*)(g_v + kvbase + (size_t)j * D_MODEL);
            den = den * corr + wgt;
            ax = ax * corr + wgt * vv.x;
            ay = ay * corr + wgt * vv.y;
            mx = nm;
        }
        float inv = 1.f / den;
        ax *= inv; ay *= inv;
    } else {
        int r0 = g_ridx[2 * i], r1 = g_ridx[2 * i + 1];
        float p[11];
        int js[11];
        unsigned vm = 0;
#pragma unroll
        for (int s = 0; s < 11; ++s) {
            int j; bool valid;
            if (s == 0)      { j = 0; valid = true; }
            else if (s <= 8) { j = i - 8 + s; valid = (j >= 1); }
            else {
                j = (s == 9) ? r0 : r1;
                valid = (j >= 1) && (j <= i - 8) && ((s == 9) || (j != r0));
            }
            float sv = -1e30f;
            if (valid) {
                float2 kv = *(const float2*)(g_k + kvbase + (size_t)j * D_MODEL);
                float d = qv.x * kv.x + qv.y * kv.y;
#pragma unroll
                for (int off = 16; off; off >>= 1) d += __shfl_xor_sync(0xffffffffu, d, off);
                sv = d * scale;
                vm |= 1u << s;
            }
            p[s] = sv;
            js[s] = j;
        }
        float mx = p[0];
#pragma unroll
        for (int s = 1; s < 11; ++s) mx = fmaxf(mx, p[s]);
        float den = 0.f;
#pragma unroll
        for (int s = 0; s < 11; ++s) {
            p[s] = ((vm >> s) & 1u) ? expf(p[s] - mx) : 0.f;
            den += p[s];
        }
        float inv = 1.f / den;
        ax = ay = 0.f;
#pragma unroll
        for (int s = 0; s < 11; ++s) {
            if ((vm >> s) & 1u) {
                float2 vv = *(const float2*)(g_v + kvbase + (size_t)js[s] * D_MODEL);
                ax += p[s] * vv.x;
                ay += p[s] * vv.y;
            }
        }
        ax *= inv; ay *= inv;
    }
    *(float2*)(g_attn + rowq + 2 * lane) = make_float2(ax, ay);
}

// ---------------- launch ------------------------------------------------------
extern "C" void kernel_launch(void* const* d_in, const int* in_sizes, int n_in,
                              void* d_out, int out_size) {
    const float* x     = (const float*)d_in[0];
    const float* freqs = (const float*)d_in[1];
    const float* w[4]  = {(const float*)d_in[2], (const float*)d_in[3],
                          (const float*)d_in[4], (const float*)d_in[5]};
    float* out = (float*)d_out;

    float *qp, *kp, *vp, *ap;
    cudaGetSymbolAddress((void**)&qp, g_q);
    cudaGetSymbolAddress((void**)&kp, g_k);
    cudaGetSymbolAddress((void**)&vp, g_v);
    cudaGetSymbolAddress((void**)&ap, g_attn);
    __nv_bfloat16 *xhi, *xlo, *ahi, *alo, *whi, *wlo;
    cudaGetSymbolAddress((void**)&xhi, g_xhi);
    cudaGetSymbolAddress((void**)&xlo, g_xlo);
    cudaGetSymbolAddress((void**)&ahi, g_ahi);
    cudaGetSymbolAddress((void**)&alo, g_alo);
    cudaGetSymbolAddress((void**)&whi, g_whi);
    cudaGetSymbolAddress((void**)&wlo, g_wlo);

    const int NW = D_MODEL * D_MODEL;   // 1M
    const int NX = M_TOTAL * D_MODEL;   // 4M

    split_kernel<<<NX / 256, 256>>>(x, xhi, xlo, NX);
    for (int i = 0; i < 4; ++i)
        split_kernel<<<NW / 256, 256>>>(w[i], whi + (size_t)i * NW, wlo + (size_t)i * NW, NW);

    dim3 gg(1024 / 128, M_TOTAL / 128);   // (8, 32) = 256 CTAs
    gemm_hmma3_kernel<<<gg, 256>>>(xhi, xlo, whi + 0 * (size_t)NW, wlo + 0 * (size_t)NW, qp);
    gemm_hmma3_kernel<<<gg, 256>>>(xhi, xlo, whi + 1 * (size_t)NW, wlo + 1 * (size_t)NW, kp);
    gemm_hmma3_kernel<<<gg, 256>>>(xhi, xlo, whi + 2 * (size_t)NW, wlo + 2 * (size_t)NW, vp);

    rope_kernel<<<8192, 256>>>(freqs);
    ridx_kernel<<<8, 256>>>();
    attn_kernel<<<8192, 256>>>();

    split_kernel<<<NX / 256, 256>>>(ap, ahi, alo, NX);
    gemm_hmma3_kernel<<<gg, 256>>>(ahi, alo, whi + 3 * (size_t)NW, wlo + 3 * (size_t)NW, out);
}

// round 5
// speedup vs baseline: 1.5041x; 1.0575x over previous
#include <cuda_runtime.h>
#include <cuda_bf16.h>
#include <math.h>
#include <stdint.h>

#define D_MODEL 1024
#define N_HEADS 16
#define HEAD_DIM 64
#define SEQ_L 2048
#define BATCH 2
#define M_TOTAL (BATCH * SEQ_L)   // 4096
#define NW (D_MODEL * D_MODEL)    // 1M
#define NX (M_TOTAL * D_MODEL)    // 4M

// ---------------- scratch (static device globals; no allocation) -------------
__device__ __align__(256) float g_q[NX];
__device__ __align__(256) float g_k[NX];
__device__ __align__(256) float g_v[NX];
__device__ int g_ridx[SEQ_L * 2];

__device__ __align__(256) __nv_bfloat16 g_xhi[NX];
__device__ __align__(256) __nv_bfloat16 g_xlo[NX];
__device__ __align__(256) __nv_bfloat16 g_ahi[NX];
__device__ __align__(256) __nv_bfloat16 g_alo[NX];
__device__ __align__(256) __nv_bfloat16 g_whi[4 * NW];
__device__ __align__(256) __nv_bfloat16 g_wlo[4 * NW];

// ---------------- baseline-ISA helpers ---------------------------------------
__device__ __forceinline__ uint32_t smem_to_u32(const void* p) {
    uint32_t a;
    asm("{ .reg .u64 t; cvta.to.shared.u64 t, %1; cvt.u32.u64 %0, t; }" : "=r"(a) : "l"(p));
    return a;
}
__device__ __forceinline__ void cp16(uint32_t s, const void* g) {
    asm volatile("cp.async.cg.shared.global [%0], [%1], 16;" :: "r"(s), "l"(g) : "memory");
}
#define CP_COMMIT() asm volatile("cp.async.commit_group;" ::: "memory")
#define CP_WAIT0()  asm volatile("cp.async.wait_group 0;" ::: "memory")

__device__ __forceinline__ void ldm4(uint32_t (&r)[4], uint32_t addr) {
    asm volatile("ldmatrix.sync.aligned.m8n8.x4.shared.b16 {%0,%1,%2,%3}, [%4];"
                 : "=r"(r[0]), "=r"(r[1]), "=r"(r[2]), "=r"(r[3]) : "r"(addr));
}
__device__ __forceinline__ void mma16816(float (&d)[4], const uint32_t (&a)[4],
                                         uint32_t b0, uint32_t b1) {
    asm volatile(
        "mma.sync.aligned.m16n8k16.row.col.f32.bf16.bf16.f32 "
        "{%0,%1,%2,%3}, {%4,%5,%6,%7}, {%8,%9}, {%0,%1,%2,%3};"
        : "+f"(d[0]), "+f"(d[1]), "+f"(d[2]), "+f"(d[3])
        : "r"(a[0]), "r"(a[1]), "r"(a[2]), "r"(a[3]), "r"(b0), "r"(b1));
}

// ---------------- Threefry-2x32 (JAX partitionable) --------------------------
__device__ __forceinline__ unsigned rotl32(unsigned x, int d) {
    return (x << d) | (x >> (32 - d));
}
__device__ void threefry2x32(unsigned k0, unsigned k1, unsigned c0, unsigned c1,
                             unsigned& o0, unsigned& o1) {
    unsigned k2 = k0 ^ k1 ^ 0x1BD11BDAu;
    unsigned x0 = c0 + k0, x1 = c1 + k1;
#define TF_RND(r) { x0 += x1; x1 = rotl32(x1, (r)); x1 ^= x0; }
    TF_RND(13) TF_RND(15) TF_RND(26) TF_RND(6)
    x0 += k1; x1 += k2 + 1u;
    TF_RND(17) TF_RND(29) TF_RND(16) TF_RND(24)
    x0 += k2; x1 += k0 + 2u;
    TF_RND(13) TF_RND(15) TF_RND(26) TF_RND(6)
    x0 += k0; x1 += k1 + 3u;
    TF_RND(17) TF_RND(29) TF_RND(16) TF_RND(24)
    x0 += k1; x1 += k2 + 4u;
    TF_RND(13) TF_RND(15) TF_RND(26) TF_RND(6)
    x0 += k2; x1 += k0 + 5u;
#undef TF_RND
    o0 = x0; o1 = x1;
}
__global__ void ridx_kernel() {
    int i = blockIdx.x * blockDim.x + threadIdx.x;
    if (i >= SEQ_L) return;
#pragma unroll
    for (int c = 0; c < 2; ++c) {
        unsigned n = (unsigned)(2 * i + c);
        unsigned o0, o1;
        threefry2x32(0u, 42u, 0u, n, o0, o1);
        unsigned bits = o0 ^ o1;
        float u = __uint_as_float((bits >> 9) | 0x3f800000u) - 1.0f;
        g_ridx[2 * i + c] = (int)(u * (float)(i + 1));
    }
}

// ---------------- fp32 -> bf16 hi/lo splits -----------------------------------
__global__ __launch_bounds__(256) void split_x_kernel(const float* __restrict__ src,
                                                      __nv_bfloat16* __restrict__ hi,
                                                      __nv_bfloat16* __restrict__ lo) {
    int i = blockIdx.x * 256 + threadIdx.x;
    float v = src[i];
    __nv_bfloat16 h = __float2bfloat16(v);
    hi[i] = h;
    lo[i] = __float2bfloat16(v - __bfloat162float(h));
}
__global__ __launch_bounds__(256) void split_w_kernel(const float* __restrict__ w0,
                                                      const float* __restrict__ w1,
                                                      const float* __restrict__ w2,
                                                      const float* __restrict__ w3,
                                                      __nv_bfloat16* __restrict__ hi,
                                                      __nv_bfloat16* __restrict__ lo) {
    int i = blockIdx.x * 256 + threadIdx.x;
    int wi = i >> 20;
    int off = i & (NW - 1);
    const float* src = (wi == 0) ? w0 : (wi == 1) ? w1 : (wi == 2) ? w2 : w3;
    float v = src[off];
    __nv_bfloat16 h = __float2bfloat16(v);
    hi[i] = h;
    lo[i] = __float2bfloat16(v - __bfloat162float(h));
}

// ---------------- HMMA GEMM: C[M,1024] = A[M,1024] * B[1024,1024]^T ----------
// 3-term compensated bf16: C = Ahi*Bhi + Alo*Bhi + Ahi*Blo (48 K-stages of 64).
// CTA tile 128x128, 256 thr, warps 4(M) x 2(N), warp tile 32x64 (m16n8k16).
// smem: 2 stages x (A 16KB + B 16KB), 128B rows, SW128 XOR-8 swizzle.
// blockIdx.z selects weight slice + output; rope fused into epilogue for z<2.
#define GEMM_SMEM (2 * 32768)

__global__ __launch_bounds__(256, 2) void gemm_hmma3_kernel(
    const __nv_bfloat16* __restrict__ Ahi, const __nv_bfloat16* __restrict__ Alo,
    const __nv_bfloat16* __restrict__ Wh_base, const __nv_bfloat16* __restrict__ Wl_base,
    float* __restrict__ out0, float* __restrict__ out1, float* __restrict__ out2,
    const float* __restrict__ freqs, int rope) {
    extern __shared__ __align__(128) char smem[];

    const int tid = threadIdx.x;
    const int lane = tid & 31;
    const int wid = tid >> 5;
    const int wm = wid >> 1;          // 0..3
    const int wn = wid & 1;           // 0..1
    const int Mbase = blockIdx.y * 128;
    const int Nbase = blockIdx.x * 128;
    const int z = blockIdx.z;

    const __nv_bfloat16* Bhi = Wh_base + (size_t)z * NW;
    const __nv_bfloat16* Blo = Wl_base + (size_t)z * NW;
    float* C = (z == 0) ? out0 : (z == 1) ? out1 : out2;

    const __nv_bfloat16* Asrc[3] = {Ahi, Alo, Ahi};
    const __nv_bfloat16* Bsrc[3] = {Bhi, Bhi, Blo};

    // stage buffers: [buf] A at buf*32768, B at buf*32768 + 16384
    uint32_t sbase = smem_to_u32(smem);

    // cp.async mapping: 1024 16B-chunks per tensor per stage; 4 per thread.
    // chunk id -> row r = id>>3, chunk16 c = id&7 ; smem off = r*128 + ((c^(r&7))<<4)
    uint32_t sw_st[4];
    int ld_r[4], ld_c[4];
#pragma unroll
    for (int it = 0; it < 4; ++it) {
        int id = it * 256 + tid;
        int r = id >> 3, c = id & 7;
        ld_r[it] = r; ld_c[it] = c;
        sw_st[it] = (uint32_t)(r * 128 + ((c ^ (r & 7)) << 4));
    }

    float acc[2][8][4];
#pragma unroll
    for (int mt = 0; mt < 2; ++mt)
#pragma unroll
        for (int np = 0; np < 8; ++np)
#pragma unroll
            for (int e = 0; e < 4; ++e) acc[mt][np][e] = 0.f;

    // ldmatrix fixed lane components
    const int arow_l = lane & 15;          // A row within 16
    const int achk_l = lane >> 4;          // A chunk16 lsb
    const int brow_l = (lane & 7) + ((lane >> 4) << 3);
    const int bchk_l = (lane >> 3) & 1;

    // prologue: stage 0 (term 0, kt 0)
    {
        const __nv_bfloat16* A = Asrc[0];
        const __nv_bfloat16* B = Bsrc[0];
#pragma unroll
        for (int it = 0; it < 4; ++it) {
            cp16(sbase + sw_st[it], A + (size_t)(Mbase + ld_r[it]) * 1024 + ld_c[it] * 8);
            cp16(sbase + 16384 + sw_st[it], B + (size_t)(Nbase + ld_r[it]) * 1024 + ld_c[it] * 8);
        }
        CP_COMMIT();
    }

    for (int g = 0; g < 48; ++g) {
        const int buf = g & 1;
        const uint32_t sA = sbase + buf * 32768;
        const uint32_t sB = sA + 16384;
        CP_WAIT0();
        __syncthreads();

        if (g + 1 < 48) {
            const int gn = g + 1;
            const int term = gn >> 4, kt = gn & 15;
            const __nv_bfloat16* A = Asrc[term];
            const __nv_bfloat16* B = Bsrc[term];
            const int ko = kt * 64;
            const uint32_t dA = sbase + (buf ^ 1) * 32768;
#pragma unroll
            for (int it = 0; it < 4; ++it) {
                cp16(dA + sw_st[it], A + (size_t)(Mbase + ld_r[it]) * 1024 + ko + ld_c[it] * 8);
                cp16(dA + 16384 + sw_st[it], B + (size_t)(Nbase + ld_r[it]) * 1024 + ko + ld_c[it] * 8);
            }
            CP_COMMIT();
        }

#pragma unroll
        for (int ks = 0; ks < 4; ++ks) {
            uint32_t afr[2][4];
#pragma unroll
            for (int mt = 0; mt < 2; ++mt) {
                int r = wm * 32 + mt * 16 + arow_l;
                int c = ks * 2 + achk_l;
                ldm4(afr[mt], sA + (uint32_t)(r * 128 + ((c ^ (r & 7)) << 4)));
            }
            uint32_t bfr[4][4];
#pragma unroll
            for (int p = 0; p < 4; ++p) {
                int r = wn * 64 + p * 16 + brow_l;
                int c = ks * 2 + bchk_l;
                ldm4(bfr[p], sB + (uint32_t)(r * 128 + ((c ^ (r & 7)) << 4)));
            }
#pragma unroll
            for (int mt = 0; mt < 2; ++mt)
#pragma unroll
                for (int p = 0; p < 4; ++p) {
                    mma16816(acc[mt][2 * p],     afr[mt], bfr[p][0], bfr[p][1]);
                    mma16816(acc[mt][2 * p + 1], afr[mt], bfr[p][2], bfr[p][3]);
                }
        }
        __syncthreads();
    }

    // epilogue (+ fused RoPE for q,k): thread owns column pair (nc, nc+1), nc even
    const int do_rope = rope && (z < 2);
#pragma unroll
    for (int mt = 0; mt < 2; ++mt) {
        int mr = Mbase + wm * 32 + mt * 16 + (lane >> 2);
#pragma unroll
        for (int np = 0; np < 8; ++np) {
            int nc = Nbase + wn * 64 + np * 8 + (lane & 3) * 2;
            float e0 = acc[mt][np][0], e1 = acc[mt][np][1];
            float e2 = acc[mt][np][2], e3 = acc[mt][np][3];
            if (do_rope) {
                int j = (nc & 63) >> 1;
                int t0 = mr & (SEQ_L - 1);
                int t1 = (mr + 8) & (SEQ_L - 1);
                float sn, cs;
                sincosf(freqs[t0 * 32 + j], &sn, &cs);
                float r0 = e0 * cs - e1 * sn, r1 = e0 * sn + e1 * cs;
                e0 = r0; e1 = r1;
                sincosf(freqs[t1 * 32 + j], &sn, &cs);
                float r2 = e2 * cs - e3 * sn, r3 = e2 * sn + e3 * cs;
                e2 = r2; e3 = r3;
            }
            float* p0 = C + (size_t)mr * 1024 + nc;
            p0[0] = e0; p0[1] = e1;
            float* p1 = p0 + 8 * 1024;
            p1[0] = e2; p1[1] = e3;
        }
    }
}

// ---------------- Sparse BigBird attention (writes bf16 hi/lo) ---------------
__global__ __launch_bounds__(256) void attn_kernel() {
    int gtid = blockIdx.x * 256 + threadIdx.x;
    int w = gtid >> 5;
    int lane = gtid & 31;
    int i = w & (SEQ_L - 1);
    int bh = w >> 11;
    int h = bh & (N_HEADS - 1);
    int b = bh >> 4;

    size_t rowq = ((size_t)(b * SEQ_L + i)) * D_MODEL + h * HEAD_DIM;
    float2 qv = *(const float2*)(g_q + rowq + 2 * lane);
    size_t kvbase = ((size_t)b * SEQ_L) * D_MODEL + h * HEAD_DIM + 2 * lane;
    const float scale = 0.125f;
    float ax, ay;

    if (i == 0) {
        float mx = -1e30f, den = 0.f;
        ax = ay = 0.f;
        for (int j = 0; j < SEQ_L; ++j) {
            float2 kv = *(const float2*)(g_k + kvbase + (size_t)j * D_MODEL);
            float d = qv.x * kv.x + qv.y * kv.y;
#pragma unroll
            for (int off = 16; off; off >>= 1) d += __shfl_xor_sync(0xffffffffu, d, off);
            float s = d * scale;
            float nm = fmaxf(mx, s);
            float corr = expf(mx - nm);
            float wgt = expf(s - nm);
            float2 vv = *(const float2*)(g_v + kvbase + (size_t)j * D_MODEL);
            den = den * corr + wgt;
            ax = ax * corr + wgt * vv.x;
            ay = ay * corr + wgt * vv.y;
            mx = nm;
        }
        float inv = 1.f / den;
        ax *= inv; ay *= inv;
    } else {
        int r0 = g_ridx[2 * i], r1 = g_ridx[2 * i + 1];
        float p[11];
        int js[11];
        unsigned vm = 0;
#pragma unroll
        for (int s = 0; s < 11; ++s) {
            int j; bool valid;
            if (s == 0)      { j = 0; valid = true; }
            else if (s <= 8) { j = i - 8 + s; valid = (j >= 1); }
            else {
                j = (s == 9) ? r0 : r1;
                valid = (j >= 1) && (j <= i - 8) && ((s == 9) || (j != r0));
            }
            float sv = -1e30f;
            if (valid) {
                float2 kv = *(const float2*)(g_k + kvbase + (size_t)j * D_MODEL);
                float d = qv.x * kv.x + qv.y * kv.y;
#pragma unroll
                for (int off = 16; off; off >>= 1) d += __shfl_xor_sync(0xffffffffu, d, off);
                sv = d * scale;
                vm |= 1u << s;
            }
            p[s] = sv;
            js[s] = j;
        }
        float mx = p[0];
#pragma unroll
        for (int s = 1; s < 11; ++s) mx = fmaxf(mx, p[s]);
        float den = 0.f;
#pragma unroll
        for (int s = 0; s < 11; ++s) {
            p[s] = ((vm >> s) & 1u) ? expf(p[s] - mx) : 0.f;
            den += p[s];
        }
        float inv = 1.f / den;
        ax = ay = 0.f;
#pragma unroll
        for (int s = 0; s < 11; ++s) {
            if ((vm >> s) & 1u) {
                float2 vv = *(const float2*)(g_v + kvbase + (size_t)js[s] * D_MODEL);
                ax += p[s] * vv.x;
                ay += p[s] * vv.y;
            }
        }
        ax *= inv; ay *= inv;
    }
    // write bf16 hi/lo directly (input to the output-projection GEMM)
    __nv_bfloat16 hx = __float2bfloat16(ax);
    __nv_bfloat16 hy = __float2bfloat16(ay);
    size_t o = rowq + 2 * lane;
    g_ahi[o]     = hx;
    g_ahi[o + 1] = hy;
    g_alo[o]     = __float2bfloat16(ax - __bfloat162float(hx));
    g_alo[o + 1] = __float2bfloat16(ay - __bfloat162float(hy));
}

// ---------------- launch ------------------------------------------------------
extern "C" void kernel_launch(void* const* d_in, const int* in_sizes, int n_in,
                              void* d_out, int out_size) {
    const float* x     = (const float*)d_in[0];
    const float* freqs = (const float*)d_in[1];
    const float* wq    = (const float*)d_in[2];
    const float* wk    = (const float*)d_in[3];
    const float* wv    = (const float*)d_in[4];
    const float* wo    = (const float*)d_in[5];
    float* out = (float*)d_out;

    float *qp, *kp, *vp;
    cudaGetSymbolAddress((void**)&qp, g_q);
    cudaGetSymbolAddress((void**)&kp, g_k);
    cudaGetSymbolAddress((void**)&vp, g_v);
    __nv_bfloat16 *xhi, *xlo, *ahi, *alo, *whi, *wlo;
    cudaGetSymbolAddress((void**)&xhi, g_xhi);
    cudaGetSymbolAddress((void**)&xlo, g_xlo);
    cudaGetSymbolAddress((void**)&ahi, g_ahi);
    cudaGetSymbolAddress((void**)&alo, g_alo);
    cudaGetSymbolAddress((void**)&whi, g_whi);
    cudaGetSymbolAddress((void**)&wlo, g_wlo);

    cudaFuncSetAttribute(gemm_hmma3_kernel,
                         cudaFuncAttributeMaxDynamicSharedMemorySize, GEMM_SMEM);

    split_x_kernel<<<NX / 256, 256>>>(x, xhi, xlo);
    split_w_kernel<<<4 * NW / 256, 256>>>(wq, wk, wv, wo, whi, wlo);
    ridx_kernel<<<8, 256>>>();

    dim3 gqkv(1024 / 128, M_TOTAL / 128, 3);   // (8, 32, 3)
    gemm_hmma3_kernel<<<gqkv, 256, GEMM_SMEM>>>(xhi, xlo, whi, wlo,
                                                qp, kp, vp, freqs, 1);

    attn_kernel<<<8192, 256>>>();

    dim3 go(1024 / 128, M_TOTAL / 128, 1);
    gemm_hmma3_kernel<<<go, 256, GEMM_SMEM>>>(ahi, alo, whi + 3 * (size_t)NW,
                                              wlo + 3 * (size_t)NW,
                                              out, out, out, freqs, 0);
}

// round 6
// speedup vs baseline: 3.7027x; 2.4618x over previous
#include <cuda_runtime.h>
#include <cuda_bf16.h>
#include <math.h>
#include <stdint.h>

#define D_MODEL 1024
#define N_HEADS 16
#define HEAD_DIM 64
#define SEQ_L 2048
#define BATCH 2
#define M_TOTAL (BATCH * SEQ_L)   // 4096
#define NW (D_MODEL * D_MODEL)    // 1M
#define NX (M_TOTAL * D_MODEL)    // 4M

// ---------------- scratch (static device globals; no allocation) -------------
__device__ __align__(256) float g_q[NX];
__device__ __align__(256) float g_k[NX];
__device__ __align__(256) float g_v[NX];
__device__ int g_ridx[SEQ_L * 2];

__device__ __align__(256) __nv_bfloat16 g_xhi[NX];
__device__ __align__(256) __nv_bfloat16 g_xlo[NX];
__device__ __align__(256) __nv_bfloat16 g_ahi[NX];
__device__ __align__(256) __nv_bfloat16 g_alo[NX];
__device__ __align__(256) __nv_bfloat16 g_whi[4 * NW];
__device__ __align__(256) __nv_bfloat16 g_wlo[4 * NW];

// ---------------- baseline-ISA helpers ---------------------------------------
__device__ __forceinline__ uint32_t smem_to_u32(const void* p) {
    uint32_t a;
    asm("{ .reg .u64 t; cvta.to.shared.u64 t, %1; cvt.u32.u64 %0, t; }" : "=r"(a) : "l"(p));
    return a;
}
__device__ __forceinline__ void cp16(uint32_t s, const void* g) {
    asm volatile("cp.async.cg.shared.global [%0], [%1], 16;" :: "r"(s), "l"(g) : "memory");
}
#define CP_COMMIT() asm volatile("cp.async.commit_group;" ::: "memory")
#define CP_WAIT1()  asm volatile("cp.async.wait_group 1;" ::: "memory")

__device__ __forceinline__ void ldm4(uint32_t (&r)[4], uint32_t addr) {
    asm volatile("ldmatrix.sync.aligned.m8n8.x4.shared.b16 {%0,%1,%2,%3}, [%4];"
                 : "=r"(r[0]), "=r"(r[1]), "=r"(r[2]), "=r"(r[3]) : "r"(addr));
}
__device__ __forceinline__ void mma16816(float (&d)[4], const uint32_t (&a)[4],
                                         uint32_t b0, uint32_t b1) {
    asm volatile(
        "mma.sync.aligned.m16n8k16.row.col.f32.bf16.bf16.f32 "
        "{%0,%1,%2,%3}, {%4,%5,%6,%7}, {%8,%9}, {%0,%1,%2,%3};"
        : "+f"(d[0]), "+f"(d[1]), "+f"(d[2]), "+f"(d[3])
        : "r"(a[0]), "r"(a[1]), "r"(a[2]), "r"(a[3]), "r"(b0), "r"(b1));
}

// ---------------- Threefry-2x32 (JAX partitionable) --------------------------
__device__ __forceinline__ unsigned rotl32(unsigned x, int d) {
    return (x << d) | (x >> (32 - d));
}
__device__ void threefry2x32(unsigned k0, unsigned k1, unsigned c0, unsigned c1,
                             unsigned& o0, unsigned& o1) {
    unsigned k2 = k0 ^ k1 ^ 0x1BD11BDAu;
    unsigned x0 = c0 + k0, x1 = c1 + k1;
#define TF_RND(r) { x0 += x1; x1 = rotl32(x1, (r)); x1 ^= x0; }
    TF_RND(13) TF_RND(15) TF_RND(26) TF_RND(6)
    x0 += k1; x1 += k2 + 1u;
    TF_RND(17) TF_RND(29) TF_RND(16) TF_RND(24)
    x0 += k2; x1 += k0 + 2u;
    TF_RND(13) TF_RND(15) TF_RND(26) TF_RND(6)
    x0 += k0; x1 += k1 + 3u;
    TF_RND(17) TF_RND(29) TF_RND(16) TF_RND(24)
    x0 += k1; x1 += k2 + 4u;
    TF_RND(13) TF_RND(15) TF_RND(26) TF_RND(6)
    x0 += k2; x1 += k0 + 5u;
#undef TF_RND
    o0 = x0; o1 = x1;
}
__global__ void ridx_kernel() {
    int i = blockIdx.x * blockDim.x + threadIdx.x;
    if (i >= SEQ_L) return;
#pragma unroll
    for (int c = 0; c < 2; ++c) {
        unsigned n = (unsigned)(2 * i + c);
        unsigned o0, o1;
        threefry2x32(0u, 42u, 0u, n, o0, o1);
        unsigned bits = o0 ^ o1;
        float u = __uint_as_float((bits >> 9) | 0x3f800000u) - 1.0f;
        g_ridx[2 * i + c] = (int)(u * (float)(i + 1));
    }
}

// ---------------- fp32 -> bf16 hi/lo splits -----------------------------------
__global__ __launch_bounds__(256) void split_x_kernel(const float* __restrict__ src,
                                                      __nv_bfloat16* __restrict__ hi,
                                                      __nv_bfloat16* __restrict__ lo) {
    int i = blockIdx.x * 256 + threadIdx.x;
    float v = src[i];
    __nv_bfloat16 h = __float2bfloat16(v);
    hi[i] = h;
    lo[i] = __float2bfloat16(v - __bfloat162float(h));
}
__global__ __launch_bounds__(256) void split_w_kernel(const float* __restrict__ w0,
                                                      const float* __restrict__ w1,
                                                      const float* __restrict__ w2,
                                                      const float* __restrict__ w3,
                                                      __nv_bfloat16* __restrict__ hi,
                                                      __nv_bfloat16* __restrict__ lo) {
    int i = blockIdx.x * 256 + threadIdx.x;
    int wi = i >> 20;
    int off = i & (NW - 1);
    const float* src = (wi == 0) ? w0 : (wi == 1) ? w1 : (wi == 2) ? w2 : w3;
    float v = src[off];
    __nv_bfloat16 h = __float2bfloat16(v);
    hi[i] = h;
    lo[i] = __float2bfloat16(v - __bfloat162float(h));
}

// ---------------- HMMA GEMM (3-stage cp.async pipeline) ----------------------
// C[M,1024] = A[M,1024] * B[1024,1024]^T, 3-term compensated bf16.
// 48 K-stages of 64; CTA tile 128x128; warps 4(M) x 2(N).
// smem: 3 stages x (A 16KB + B 16KB) = 96KB, 128B rows, XOR-8 swizzle.
#define GEMM_SMEM (3 * 32768)

__global__ __launch_bounds__(256, 2) void gemm_hmma3_kernel(
    const __nv_bfloat16* __restrict__ Ahi, const __nv_bfloat16* __restrict__ Alo,
    const __nv_bfloat16* __restrict__ Wh_base, const __nv_bfloat16* __restrict__ Wl_base,
    float* __restrict__ out0, float* __restrict__ out1, float* __restrict__ out2,
    const float* __restrict__ freqs, int rope) {
    extern __shared__ __align__(128) char smem[];

    const int tid = threadIdx.x;
    const int lane = tid & 31;
    const int wid = tid >> 5;
    const int wm = wid >> 1;
    const int wn = wid & 1;
    const int Mbase = blockIdx.y * 128;
    const int Nbase = blockIdx.x * 128;
    const int z = blockIdx.z;

    const __nv_bfloat16* Bhi = Wh_base + (size_t)z * NW;
    const __nv_bfloat16* Blo = Wl_base + (size_t)z * NW;
    float* C = (z == 0) ? out0 : (z == 1) ? out1 : out2;

    const __nv_bfloat16* Asrc[3] = {Ahi, Alo, Ahi};
    const __nv_bfloat16* Bsrc[3] = {Bhi, Bhi, Blo};

    uint32_t sbase = smem_to_u32(smem);

    uint32_t sw_st[4];
    int ld_r[4], ld_c[4];
#pragma unroll
    for (int it = 0; it < 4; ++it) {
        int id = it * 256 + tid;
        int r = id >> 3, c = id & 7;
        ld_r[it] = r; ld_c[it] = c;
        sw_st[it] = (uint32_t)(r * 128 + ((c ^ (r & 7)) << 4));
    }

    float acc[2][8][4];
#pragma unroll
    for (int mt = 0; mt < 2; ++mt)
#pragma unroll
        for (int np = 0; np < 8; ++np)
#pragma unroll
            for (int e = 0; e < 4; ++e) acc[mt][np][e] = 0.f;

    const int arow_l = lane & 15;
    const int achk_l = lane >> 4;
    const int brow_l = (lane & 7) + ((lane >> 4) << 3);
    const int bchk_l = (lane >> 3) & 1;

    // prologue: stages 0, 1
#pragma unroll
    for (int ps = 0; ps < 2; ++ps) {
        const int term = ps >> 4, kt = ps & 15;
        const __nv_bfloat16* A = Asrc[term];
        const __nv_bfloat16* B = Bsrc[term];
        const int ko = kt * 64;
        const uint32_t dst = sbase + ps * 32768;
#pragma unroll
        for (int it = 0; it < 4; ++it) {
            cp16(dst + sw_st[it], A + (size_t)(Mbase + ld_r[it]) * 1024 + ko + ld_c[it] * 8);
            cp16(dst + 16384 + sw_st[it], B + (size_t)(Nbase + ld_r[it]) * 1024 + ko + ld_c[it] * 8);
        }
        CP_COMMIT();
    }

    for (int g = 0; g < 48; ++g) {
        const int buf = g % 3;
        const uint32_t sA = sbase + buf * 32768;
        const uint32_t sB = sA + 16384;
        CP_WAIT1();           // group g complete (g+1 may remain in flight)
        __syncthreads();      // all warps done with compute(g-1) -> buffer (g+2)%3 free

        {
            const int gn = g + 2;
            if (gn < 48) {
                const int term = gn >> 4, kt = gn & 15;
                const __nv_bfloat16* A = Asrc[term];
                const __nv_bfloat16* B = Bsrc[term];
                const int ko = kt * 64;
                const uint32_t dst = sbase + (gn % 3) * 32768;
#pragma unroll
                for (int it = 0; it < 4; ++it) {
                    cp16(dst + sw_st[it], A + (size_t)(Mbase + ld_r[it]) * 1024 + ko + ld_c[it] * 8);
                    cp16(dst + 16384 + sw_st[it], B + (size_t)(Nbase + ld_r[it]) * 1024 + ko + ld_c[it] * 8);
                }
            }
            CP_COMMIT();      // commit (possibly empty) to keep group accounting
        }

#pragma unroll
        for (int ks = 0; ks < 4; ++ks) {
            uint32_t afr[2][4];
#pragma unroll
            for (int mt = 0; mt < 2; ++mt) {
                int r = wm * 32 + mt * 16 + arow_l;
                int c = ks * 2 + achk_l;
                ldm4(afr[mt], sA + (uint32_t)(r * 128 + ((c ^ (r & 7)) << 4)));
            }
            uint32_t bfr[4][4];
#pragma unroll
            for (int p = 0; p < 4; ++p) {
                int r = wn * 64 + p * 16 + brow_l;
                int c = ks * 2 + bchk_l;
                ldm4(bfr[p], sB + (uint32_t)(r * 128 + ((c ^ (r & 7)) << 4)));
            }
#pragma unroll
            for (int mt = 0; mt < 2; ++mt)
#pragma unroll
                for (int p = 0; p < 4; ++p) {
                    mma16816(acc[mt][2 * p],     afr[mt], bfr[p][0], bfr[p][1]);
                    mma16816(acc[mt][2 * p + 1], afr[mt], bfr[p][2], bfr[p][3]);
                }
        }
    }

    // epilogue (+ fused RoPE for q,k)
    const int do_rope = rope && (z < 2);
#pragma unroll
    for (int mt = 0; mt < 2; ++mt) {
        int mr = Mbase + wm * 32 + mt * 16 + (lane >> 2);
#pragma unroll
        for (int np = 0; np < 8; ++np) {
            int nc = Nbase + wn * 64 + np * 8 + (lane & 3) * 2;
            float e0 = acc[mt][np][0], e1 = acc[mt][np][1];
            float e2 = acc[mt][np][2], e3 = acc[mt][np][3];
            if (do_rope) {
                int j = (nc & 63) >> 1;
                int t0 = mr & (SEQ_L - 1);
                int t1 = (mr + 8) & (SEQ_L - 1);
                float sn, cs;
                sincosf(freqs[t0 * 32 + j], &sn, &cs);
                float r0 = e0 * cs - e1 * sn, r1 = e0 * sn + e1 * cs;
                e0 = r0; e1 = r1;
                sincosf(freqs[t1 * 32 + j], &sn, &cs);
                float r2 = e2 * cs - e3 * sn, r3 = e2 * sn + e3 * cs;
                e2 = r2; e3 = r3;
            }
            float* p0 = C + (size_t)mr * 1024 + nc;
            p0[0] = e0; p0[1] = e1;
            float* p1 = p0 + 8 * 1024;
            p1[0] = e2; p1[1] = e3;
        }
    }
}

// ---------------- global-row attention (i == 0), block-parallel --------------
// one block per (b, h); 8 warps x 256 keys each; flash combine in smem.
__global__ __launch_bounds__(256) void attn_global_kernel() {
    int bh = blockIdx.x;
    int h = bh & (N_HEADS - 1);
    int b = bh >> 4;
    int wid = threadIdx.x >> 5, lane = threadIdx.x & 31;

    size_t rowq = ((size_t)b * SEQ_L) * D_MODEL + h * HEAD_DIM;
    float2 qv = *(const float2*)(g_q + rowq + 2 * lane);
    size_t kvbase = rowq + 2 * lane;
    const float scale = 0.125f;

    float mx = -1e30f, den = 0.f, ax = 0.f, ay = 0.f;
    for (int j0 = wid * 256; j0 < wid * 256 + 256; j0 += 4) {
        float d[4];
        float2 vv[4];
#pragma unroll
        for (int t = 0; t < 4; ++t) {
            float2 kv = *(const float2*)(g_k + kvbase + (size_t)(j0 + t) * D_MODEL);
            vv[t] = *(const float2*)(g_v + kvbase + (size_t)(j0 + t) * D_MODEL);
            d[t] = qv.x * kv.x + qv.y * kv.y;
        }
#pragma unroll
        for (int off = 16; off; off >>= 1)
#pragma unroll
            for (int t = 0; t < 4; ++t)
                d[t] += __shfl_xor_sync(0xffffffffu, d[t], off);
        float m4 = fmaxf(fmaxf(d[0], d[1]), fmaxf(d[2], d[3])) * scale;
        float nm = fmaxf(mx, m4);
        float corr = expf(mx - nm);
        float w[4];
#pragma unroll
        for (int t = 0; t < 4; ++t) w[t] = expf(d[t] * scale - nm);
        den = den * corr + w[0] + w[1] + w[2] + w[3];
        ax = ax * corr + w[0] * vv[0].x + w[1] * vv[1].x + w[2] * vv[2].x + w[3] * vv[3].x;
        ay = ay * corr + w[0] * vv[0].y + w[1] * vv[1].y + w[2] * vv[2].y + w[3] * vv[3].y;
        mx = nm;
    }

    __shared__ float sm_m[8], sm_d[8];
    __shared__ float sm_acc[8][65];
    sm_m[wid] = mx;
    sm_d[wid] = den;
    sm_acc[wid][2 * lane] = ax;
    sm_acc[wid][2 * lane + 1] = ay;
    __syncthreads();

    if (wid == 0) {
        float gm = sm_m[0];
#pragma unroll
        for (int w2 = 1; w2 < 8; ++w2) gm = fmaxf(gm, sm_m[w2]);
        float dt = 0.f, fx = 0.f, fy = 0.f;
#pragma unroll
        for (int w2 = 0; w2 < 8; ++w2) {
            float f = expf(sm_m[w2] - gm);
            dt += sm_d[w2] * f;
            fx += sm_acc[w2][2 * lane] * f;
            fy += sm_acc[w2][2 * lane + 1] * f;
        }
        float inv = 1.f / dt;
        fx *= inv; fy *= inv;
        __nv_bfloat16 hx = __float2bfloat16(fx);
        __nv_bfloat16 hy = __float2bfloat16(fy);
        size_t o = rowq + 2 * lane;
        g_ahi[o] = hx;
        g_ahi[o + 1] = hy;
        g_alo[o] = __float2bfloat16(fx - __bfloat162float(hx));
        g_alo[o + 1] = __float2bfloat16(fy - __bfloat162float(hy));
    }
}

// ---------------- Sparse BigBird attention (i >= 1 only) ---------------------
__global__ __launch_bounds__(256) void attn_kernel() {
    int gtid = blockIdx.x * 256 + threadIdx.x;
    int w = gtid >> 5;
    int lane = gtid & 31;
    int i = w & (SEQ_L - 1);
    if (i == 0) return;   // handled by attn_global_kernel
    int bh = w >> 11;
    int h = bh & (N_HEADS - 1);
    int b = bh >> 4;

    size_t rowq = ((size_t)(b * SEQ_L + i)) * D_MODEL + h * HEAD_DIM;
    float2 qv = *(const float2*)(g_q + rowq + 2 * lane);
    size_t kvbase = ((size_t)b * SEQ_L) * D_MODEL + h * HEAD_DIM + 2 * lane;
    const float scale = 0.125f;

    int r0 = g_ridx[2 * i], r1 = g_ridx[2 * i + 1];
    float p[11];
    int js[11];
    unsigned vm = 0;
#pragma unroll
    for (int s = 0; s < 11; ++s) {
        int j; bool valid;
        if (s == 0)      { j = 0; valid = true; }
        else if (s <= 8) { j = i - 8 + s; valid = (j >= 1); }
        else {
            j = (s == 9) ? r0 : r1;
            valid = (j >= 1) && (j <= i - 8) && ((s == 9) || (j != r0));
        }
        float sv = -1e30f;
        if (valid) {
            float2 kv = *(const float2*)(g_k + kvbase + (size_t)j * D_MODEL);
            float d = qv.x * kv.x + qv.y * kv.y;
#pragma unroll
            for (int off = 16; off; off >>= 1) d += __shfl_xor_sync(0xffffffffu, d, off);
            sv = d * scale;
            vm |= 1u << s;
        }
        p[s] = sv;
        js[s] = j;
    }
    float mx = p[0];
#pragma unroll
    for (int s = 1; s < 11; ++s) mx = fmaxf(mx, p[s]);
    float den = 0.f;
#pragma unroll
    for (int s = 0; s < 11; ++s) {
        p[s] = ((vm >> s) & 1u) ? expf(p[s] - mx) : 0.f;
        den += p[s];
    }
    float inv = 1.f / den;
    float ax = 0.f, ay = 0.f;
#pragma unroll
    for (int s = 0; s < 11; ++s) {
        if ((vm >> s) & 1u) {
            float2 vv = *(const float2*)(g_v + kvbase + (size_t)js[s] * D_MODEL);
            ax += p[s] * vv.x;
            ay += p[s] * vv.y;
        }
    }
    ax *= inv; ay *= inv;

    __nv_bfloat16 hx = __float2bfloat16(ax);
    __nv_bfloat16 hy = __float2bfloat16(ay);
    size_t o = rowq + 2 * lane;
    g_ahi[o]     = hx;
    g_ahi[o + 1] = hy;
    g_alo[o]     = __float2bfloat16(ax - __bfloat162float(hx));
    g_alo[o + 1] = __float2bfloat16(ay - __bfloat162float(hy));
}

// ---------------- launch ------------------------------------------------------
extern "C" void kernel_launch(void* const* d_in, const int* in_sizes, int n_in,
                              void* d_out, int out_size) {
    const float* x     = (const float*)d_in[0];
    const float* freqs = (const float*)d_in[1];
    const float* wq    = (const float*)d_in[2];
    const float* wk    = (const float*)d_in[3];
    const float* wv    = (const float*)d_in[4];
    const float* wo    = (const float*)d_in[5];
    float* out = (float*)d_out;

    float *qp, *kp, *vp;
    cudaGetSymbolAddress((void**)&qp, g_q);
    cudaGetSymbolAddress((void**)&kp, g_k);
    cudaGetSymbolAddress((void**)&vp, g_v);
    __nv_bfloat16 *xhi, *xlo, *ahi, *alo, *whi, *wlo;
    cudaGetSymbolAddress((void**)&xhi, g_xhi);
    cudaGetSymbolAddress((void**)&xlo, g_xlo);
    cudaGetSymbolAddress((void**)&ahi, g_ahi);
    cudaGetSymbolAddress((void**)&alo, g_alo);
    cudaGetSymbolAddress((void**)&whi, g_whi);
    cudaGetSymbolAddress((void**)&wlo, g_wlo);

    cudaFuncSetAttribute(gemm_hmma3_kernel,
                         cudaFuncAttributeMaxDynamicSharedMemorySize, GEMM_SMEM);

    split_x_kernel<<<NX / 256, 256>>>(x, xhi, xlo);
    split_w_kernel<<<4 * NW / 256, 256>>>(wq, wk, wv, wo, whi, wlo);
    ridx_kernel<<<8, 256>>>();

    dim3 gqkv(1024 / 128, M_TOTAL / 128, 3);
    gemm_hmma3_kernel<<<gqkv, 256, GEMM_SMEM>>>(xhi, xlo, whi, wlo,
                                                qp, kp, vp, freqs, 1);

    attn_kernel<<<8192, 256>>>();
    attn_global_kernel<<<BATCH * N_HEADS, 256>>>();

    dim3 go(1024 / 128, M_TOTAL / 128, 1);
    gemm_hmma3_kernel<<<go, 256, GEMM_SMEM>>>(ahi, alo, whi + 3 * (size_t)NW,
                                              wlo + 3 * (size_t)NW,
                                              out, out, out, freqs, 0);
}

// round 7
// speedup vs baseline: 4.8615x; 1.3129x over previous
#include <cuda_runtime.h>
#include <cuda_fp16.h>
#include <math.h>
#include <stdint.h>

#define D_MODEL 1024
#define N_HEADS 16
#define HEAD_DIM 64
#define SEQ_L 2048
#define BATCH 2
#define M_TOTAL (BATCH * SEQ_L)   // 4096
#define NW (D_MODEL * D_MODEL)    // 1M
#define NX (M_TOTAL * D_MODEL)    // 4M

// ---------------- scratch (static device globals; no allocation) -------------
__device__ __align__(256) float g_q[NX];
__device__ __align__(256) float g_k[NX];
__device__ __align__(256) float g_v[NX];
__device__ int g_ridx[SEQ_L * 2];

__device__ __align__(256) __half g_xhi[NX];
__device__ __align__(256) __half g_xlo[NX];
__device__ __align__(256) __half g_ahi[NX];
__device__ __align__(256) __half g_alo[NX];
__device__ __align__(256) __half g_whi[4 * NW];
__device__ __align__(256) __half g_wlo[4 * NW];

// ---------------- baseline-ISA helpers ---------------------------------------
__device__ __forceinline__ uint32_t smem_to_u32(const void* p) {
    uint32_t a;
    asm("{ .reg .u64 t; cvta.to.shared.u64 t, %1; cvt.u32.u64 %0, t; }" : "=r"(a) : "l"(p));
    return a;
}
__device__ __forceinline__ void cp16(uint32_t s, const void* g) {
    asm volatile("cp.async.cg.shared.global [%0], [%1], 16;" :: "r"(s), "l"(g) : "memory");
}
#define CP_COMMIT() asm volatile("cp.async.commit_group;" ::: "memory")
#define CP_WAIT1()  asm volatile("cp.async.wait_group 1;" ::: "memory")

__device__ __forceinline__ void ldm4(uint32_t (&r)[4], uint32_t addr) {
    asm volatile("ldmatrix.sync.aligned.m8n8.x4.shared.b16 {%0,%1,%2,%3}, [%4];"
                 : "=r"(r[0]), "=r"(r[1]), "=r"(r[2]), "=r"(r[3]) : "r"(addr));
}
__device__ __forceinline__ void mma16816(float (&d)[4], const uint32_t (&a)[4],
                                         uint32_t b0, uint32_t b1) {
    asm volatile(
        "mma.sync.aligned.m16n8k16.row.col.f32.f16.f16.f32 "
        "{%0,%1,%2,%3}, {%4,%5,%6,%7}, {%8,%9}, {%0,%1,%2,%3};"
        : "+f"(d[0]), "+f"(d[1]), "+f"(d[2]), "+f"(d[3])
        : "r"(a[0]), "r"(a[1]), "r"(a[2]), "r"(a[3]), "r"(b0), "r"(b1));
}

// ---------------- Threefry-2x32 (JAX partitionable) --------------------------
__device__ __forceinline__ unsigned rotl32(unsigned x, int d) {
    return (x << d) | (x >> (32 - d));
}
__device__ void threefry2x32(unsigned k0, unsigned k1, unsigned c0, unsigned c1,
                             unsigned& o0, unsigned& o1) {
    unsigned k2 = k0 ^ k1 ^ 0x1BD11BDAu;
    unsigned x0 = c0 + k0, x1 = c1 + k1;
#define TF_RND(r) { x0 += x1; x1 = rotl32(x1, (r)); x1 ^= x0; }
    TF_RND(13) TF_RND(15) TF_RND(26) TF_RND(6)
    x0 += k1; x1 += k2 + 1u;
    TF_RND(17) TF_RND(29) TF_RND(16) TF_RND(24)
    x0 += k2; x1 += k0 + 2u;
    TF_RND(13) TF_RND(15) TF_RND(26) TF_RND(6)
    x0 += k0; x1 += k1 + 3u;
    TF_RND(17) TF_RND(29) TF_RND(16) TF_RND(24)
    x0 += k1; x1 += k2 + 4u;
    TF_RND(13) TF_RND(15) TF_RND(26) TF_RND(6)
    x0 += k2; x1 += k0 + 5u;
#undef TF_RND
    o0 = x0; o1 = x1;
}
__global__ void ridx_kernel() {
    int i = blockIdx.x * blockDim.x + threadIdx.x;
    if (i >= SEQ_L) return;
#pragma unroll
    for (int c = 0; c < 2; ++c) {
        unsigned n = (unsigned)(2 * i + c);
        unsigned o0, o1;
        threefry2x32(0u, 42u, 0u, n, o0, o1);
        unsigned bits = o0 ^ o1;
        float u = __uint_as_float((bits >> 9) | 0x3f800000u) - 1.0f;
        g_ridx[2 * i + c] = (int)(u * (float)(i + 1));
    }
}

// ---------------- fp32 -> fp16 hi/lo splits -----------------------------------
__global__ __launch_bounds__(256) void split_x_kernel(const float* __restrict__ src,
                                                      __half* __restrict__ hi,
                                                      __half* __restrict__ lo) {
    int i = blockIdx.x * 256 + threadIdx.x;
    float v = src[i];
    __half h = __float2half_rn(v);
    hi[i] = h;
    lo[i] = __float2half_rn(v - __half2float(h));
}
__global__ __launch_bounds__(256) void split_w_kernel(const float* __restrict__ w0,
                                                      const float* __restrict__ w1,
                                                      const float* __restrict__ w2,
                                                      const float* __restrict__ w3,
                                                      __half* __restrict__ hi,
                                                      __half* __restrict__ lo) {
    int i = blockIdx.x * 256 + threadIdx.x;
    int wi = i >> 20;
    int off = i & (NW - 1);
    const float* src = (wi == 0) ? w0 : (wi == 1) ? w1 : (wi == 2) ? w2 : w3;
    float v = src[off];
    __half h = __float2half_rn(v);
    hi[i] = h;
    lo[i] = __float2half_rn(v - __half2float(h));
}

// ---------------- HMMA GEMM (3-stage cp.async pipeline) ----------------------
// C[M,1024] = A[M,1024] * B[1024,1024]^T, 2-term compensated fp16:
//   C = Ahi*Bhi + Alo*Bhi      (missing Ahi*Blo ~ 2^-12 relative)
// 32 K-stages of 64; CTA tile 128x128; warps 4(M) x 2(N).
// smem: 3 stages x (A 16KB + B 16KB) = 96KB, 128B rows, XOR-8 swizzle.
#define GEMM_SMEM (3 * 32768)
#define NSTAGES 32

__global__ __launch_bounds__(256, 2) void gemm_hmma2_kernel(
    const __half* __restrict__ Ahi, const __half* __restrict__ Alo,
    const __half* __restrict__ Wh_base, const __half* __restrict__ Wl_base,
    float* __restrict__ out0, float* __restrict__ out1, float* __restrict__ out2,
    const float* __restrict__ freqs, int rope) {
    extern __shared__ __align__(128) char smem[];

    const int tid = threadIdx.x;
    const int lane = tid & 31;
    const int wid = tid >> 5;
    const int wm = wid >> 1;
    const int wn = wid & 1;
    const int Mbase = blockIdx.y * 128;
    const int Nbase = blockIdx.x * 128;
    const int z = blockIdx.z;

    const __half* Bhi = Wh_base + (size_t)z * NW;
    float* C = (z == 0) ? out0 : (z == 1) ? out1 : out2;

    const __half* Asrc[2] = {Ahi, Alo};

    uint32_t sbase = smem_to_u32(smem);

    uint32_t sw_st[4];
    int ld_r[4], ld_c[4];
#pragma unroll
    for (int it = 0; it < 4; ++it) {
        int id = it * 256 + tid;
        int r = id >> 3, c = id & 7;
        ld_r[it] = r; ld_c[it] = c;
        sw_st[it] = (uint32_t)(r * 128 + ((c ^ (r & 7)) << 4));
    }

    float acc[2][8][4];
#pragma unroll
    for (int mt = 0; mt < 2; ++mt)
#pragma unroll
        for (int np = 0; np < 8; ++np)
#pragma unroll
            for (int e = 0; e < 4; ++e) acc[mt][np][e] = 0.f;

    const int arow_l = lane & 15;
    const int achk_l = lane >> 4;
    const int brow_l = (lane & 7) + ((lane >> 4) << 3);
    const int bchk_l = (lane >> 3) & 1;

    // prologue: stages 0, 1 (both term 0)
#pragma unroll
    for (int ps = 0; ps < 2; ++ps) {
        const int ko = (ps & 15) * 64;
        const uint32_t dst = sbase + ps * 32768;
#pragma unroll
        for (int it = 0; it < 4; ++it) {
            cp16(dst + sw_st[it], Ahi + (size_t)(Mbase + ld_r[it]) * 1024 + ko + ld_c[it] * 8);
            cp16(dst + 16384 + sw_st[it], Bhi + (size_t)(Nbase + ld_r[it]) * 1024 + ko + ld_c[it] * 8);
        }
        CP_COMMIT();
    }

    for (int g = 0; g < NSTAGES; ++g) {
        const int buf = g % 3;
        const uint32_t sA = sbase + buf * 32768;
        const uint32_t sB = sA + 16384;
        CP_WAIT1();
        __syncthreads();

        {
            const int gn = g + 2;
            if (gn < NSTAGES) {
                const int term = gn >> 4, kt = gn & 15;
                const __half* A = Asrc[term];
                const int ko = kt * 64;
                const uint32_t dst = sbase + (gn % 3) * 32768;
#pragma unroll
                for (int it = 0; it < 4; ++it) {
                    cp16(dst + sw_st[it], A + (size_t)(Mbase + ld_r[it]) * 1024 + ko + ld_c[it] * 8);
                    cp16(dst + 16384 + sw_st[it], Bhi + (size_t)(Nbase + ld_r[it]) * 1024 + ko + ld_c[it] * 8);
                }
            }
            CP_COMMIT();
        }

#pragma unroll
        for (int ks = 0; ks < 4; ++ks) {
            uint32_t afr[2][4];
#pragma unroll
            for (int mt = 0; mt < 2; ++mt) {
                int r = wm * 32 + mt * 16 + arow_l;
                int c = ks * 2 + achk_l;
                ldm4(afr[mt], sA + (uint32_t)(r * 128 + ((c ^ (r & 7)) << 4)));
            }
            uint32_t bfr[4][4];
#pragma unroll
            for (int p = 0; p < 4; ++p) {
                int r = wn * 64 + p * 16 + brow_l;
                int c = ks * 2 + bchk_l;
                ldm4(bfr[p], sB + (uint32_t)(r * 128 + ((c ^ (r & 7)) << 4)));
            }
#pragma unroll
            for (int mt = 0; mt < 2; ++mt)
#pragma unroll
                for (int p = 0; p < 4; ++p) {
                    mma16816(acc[mt][2 * p],     afr[mt], bfr[p][0], bfr[p][1]);
                    mma16816(acc[mt][2 * p + 1], afr[mt], bfr[p][2], bfr[p][3]);
                }
        }
    }

    // epilogue (+ fused RoPE for q,k)
    const int do_rope = rope && (z < 2);
#pragma unroll
    for (int mt = 0; mt < 2; ++mt) {
        int mr = Mbase + wm * 32 + mt * 16 + (lane >> 2);
#pragma unroll
        for (int np = 0; np < 8; ++np) {
            int nc = Nbase + wn * 64 + np * 8 + (lane & 3) * 2;
            float e0 = acc[mt][np][0], e1 = acc[mt][np][1];
            float e2 = acc[mt][np][2], e3 = acc[mt][np][3];
            if (do_rope) {
                int j = (nc & 63) >> 1;
                int t0 = mr & (SEQ_L - 1);
                int t1 = (mr + 8) & (SEQ_L - 1);
                float sn, cs;
                sincosf(freqs[t0 * 32 + j], &sn, &cs);
                float r0 = e0 * cs - e1 * sn, r1 = e0 * sn + e1 * cs;
                e0 = r0; e1 = r1;
                sincosf(freqs[t1 * 32 + j], &sn, &cs);
                float r2 = e2 * cs - e3 * sn, r3 = e2 * sn + e3 * cs;
                e2 = r2; e3 = r3;
            }
            float* p0 = C + (size_t)mr * 1024 + nc;
            p0[0] = e0; p0[1] = e1;
            float* p1 = p0 + 8 * 1024;
            p1[0] = e2; p1[1] = e3;
        }
    }
}

// ---------------- global-row attention (i == 0), block-parallel --------------
__global__ __launch_bounds__(256) void attn_global_kernel() {
    int bh = blockIdx.x;
    int h = bh & (N_HEADS - 1);
    int b = bh >> 4;
    int wid = threadIdx.x >> 5, lane = threadIdx.x & 31;

    size_t rowq = ((size_t)b * SEQ_L) * D_MODEL + h * HEAD_DIM;
    float2 qv = *(const float2*)(g_q + rowq + 2 * lane);
    size_t kvbase = rowq + 2 * lane;
    const float scale = 0.125f;

    float mx = -1e30f, den = 0.f, ax = 0.f, ay = 0.f;
    for (int j0 = wid * 256; j0 < wid * 256 + 256; j0 += 4) {
        float d[4];
        float2 vv[4];
#pragma unroll
        for (int t = 0; t < 4; ++t) {
            float2 kv = *(const float2*)(g_k + kvbase + (size_t)(j0 + t) * D_MODEL);
            vv[t] = *(const float2*)(g_v + kvbase + (size_t)(j0 + t) * D_MODEL);
            d[t] = qv.x * kv.x + qv.y * kv.y;
        }
#pragma unroll
        for (int off = 16; off; off >>= 1)
#pragma unroll
            for (int t = 0; t < 4; ++t)
                d[t] += __shfl_xor_sync(0xffffffffu, d[t], off);
        float m4 = fmaxf(fmaxf(d[0], d[1]), fmaxf(d[2], d[3])) * scale;
        float nm = fmaxf(mx, m4);
        float corr = expf(mx - nm);
        float w[4];
#pragma unroll
        for (int t = 0; t < 4; ++t) w[t] = expf(d[t] * scale - nm);
        den = den * corr + w[0] + w[1] + w[2] + w[3];
        ax = ax * corr + w[0] * vv[0].x + w[1] * vv[1].x + w[2] * vv[2].x + w[3] * vv[3].x;
        ay = ay * corr + w[0] * vv[0].y + w[1] * vv[1].y + w[2] * vv[2].y + w[3] * vv[3].y;
        mx = nm;
    }

    __shared__ float sm_m[8], sm_d[8];
    __shared__ float sm_acc[8][65];
    sm_m[wid] = mx;
    sm_d[wid] = den;
    sm_acc[wid][2 * lane] = ax;
    sm_acc[wid][2 * lane + 1] = ay;
    __syncthreads();

    if (wid == 0) {
        float gm = sm_m[0];
#pragma unroll
        for (int w2 = 1; w2 < 8; ++w2) gm = fmaxf(gm, sm_m[w2]);
        float dt = 0.f, fx = 0.f, fy = 0.f;
#pragma unroll
        for (int w2 = 0; w2 < 8; ++w2) {
            float f = expf(sm_m[w2] - gm);
            dt += sm_d[w2] * f;
            fx += sm_acc[w2][2 * lane] * f;
            fy += sm_acc[w2][2 * lane + 1] * f;
        }
        float inv = 1.f / dt;
        fx *= inv; fy *= inv;
        __half hx = __float2half_rn(fx);
        __half hy = __float2half_rn(fy);
        size_t o = rowq + 2 * lane;
        g_ahi[o] = hx;
        g_ahi[o + 1] = hy;
        g_alo[o] = __float2half_rn(fx - __half2float(hx));
        g_alo[o + 1] = __float2half_rn(fy - __half2float(hy));
    }
}

// ---------------- Sparse BigBird attention (i >= 1 only) ---------------------
__global__ __launch_bounds__(256) void attn_kernel() {
    int gtid = blockIdx.x * 256 + threadIdx.x;
    int w = gtid >> 5;
    int lane = gtid & 31;
    int i = w & (SEQ_L - 1);
    if (i == 0) return;
    int bh = w >> 11;
    int h = bh & (N_HEADS - 1);
    int b = bh >> 4;

    size_t rowq = ((size_t)(b * SEQ_L + i)) * D_MODEL + h * HEAD_DIM;
    float2 qv = *(const float2*)(g_q + rowq + 2 * lane);
    size_t kvbase = ((size_t)b * SEQ_L) * D_MODEL + h * HEAD_DIM + 2 * lane;
    const float scale = 0.125f;

    int r0 = g_ridx[2 * i], r1 = g_ridx[2 * i + 1];
    float p[11];
    int js[11];
    unsigned vm = 0;
#pragma unroll
    for (int s = 0; s < 11; ++s) {
        int j; bool valid;
        if (s == 0)      { j = 0; valid = true; }
        else if (s <= 8) { j = i - 8 + s; valid = (j >= 1); }
        else {
            j = (s == 9) ? r0 : r1;
            valid = (j >= 1) && (j <= i - 8) && ((s == 9) || (j != r0));
        }
        float sv = -1e30f;
        if (valid) {
            float2 kv = *(const float2*)(g_k + kvbase + (size_t)j * D_MODEL);
            float d = qv.x * kv.x + qv.y * kv.y;
#pragma unroll
            for (int off = 16; off; off >>= 1) d += __shfl_xor_sync(0xffffffffu, d, off);
            sv = d * scale;
            vm |= 1u << s;
        }
        p[s] = sv;
        js[s] = j;
    }
    float mx = p[0];
#pragma unroll
    for (int s = 1; s < 11; ++s) mx = fmaxf(mx, p[s]);
    float den = 0.f;
#pragma unroll
    for (int s = 0; s < 11; ++s) {
        p[s] = ((vm >> s) & 1u) ? expf(p[s] - mx) : 0.f;
        den += p[s];
    }
    float inv = 1.f / den;
    float ax = 0.f, ay = 0.f;
#pragma unroll
    for (int s = 0; s < 11; ++s) {
        if ((vm >> s) & 1u) {
            float2 vv = *(const float2*)(g_v + kvbase + (size_t)js[s] * D_MODEL);
            ax += p[s] * vv.x;
            ay += p[s] * vv.y;
        }
    }
    ax *= inv; ay *= inv;

    __half hx = __float2half_rn(ax);
    __half hy = __float2half_rn(ay);
    size_t o = rowq + 2 * lane;
    g_ahi[o]     = hx;
    g_ahi[o + 1] = hy;
    g_alo[o]     = __float2half_rn(ax - __half2float(hx));
    g_alo[o + 1] = __float2half_rn(ay - __half2float(hy));
}

// ---------------- launch ------------------------------------------------------
extern "C" void kernel_launch(void* const* d_in, const int* in_sizes, int n_in,
                              void* d_out, int out_size) {
    const float* x     = (const float*)d_in[0];
    const float* freqs = (const float*)d_in[1];
    const float* wq    = (const float*)d_in[2];
    const float* wk    = (const float*)d_in[3];
    const float* wv    = (const float*)d_in[4];
    const float* wo    = (const float*)d_in[5];
    float* out = (float*)d_out;

    float *qp, *kp, *vp;
    cudaGetSymbolAddress((void**)&qp, g_q);
    cudaGetSymbolAddress((void**)&kp, g_k);
    cudaGetSymbolAddress((void**)&vp, g_v);
    __half *xhi, *xlo, *ahi, *alo, *whi, *wlo;
    cudaGetSymbolAddress((void**)&xhi, g_xhi);
    cudaGetSymbolAddress((void**)&xlo, g_xlo);
    cudaGetSymbolAddress((void**)&ahi, g_ahi);
    cudaGetSymbolAddress((void**)&alo, g_alo);
    cudaGetSymbolAddress((void**)&whi, g_whi);
    cudaGetSymbolAddress((void**)&wlo, g_wlo);

    cudaFuncSetAttribute(gemm_hmma2_kernel,
                         cudaFuncAttributeMaxDynamicSharedMemorySize, GEMM_SMEM);

    split_x_kernel<<<NX / 256, 256>>>(x, xhi, xlo);
    split_w_kernel<<<4 * NW / 256, 256>>>(wq, wk, wv, wo, whi, wlo);
    ridx_kernel<<<8, 256>>>();

    dim3 gqkv(1024 / 128, M_TOTAL / 128, 3);
    gemm_hmma2_kernel<<<gqkv, 256, GEMM_SMEM>>>(xhi, xlo, whi, wlo,
                                                qp, kp, vp, freqs, 1);

    attn_kernel<<<8192, 256>>>();
    attn_global_kernel<<<BATCH * N_HEADS, 256>>>();

    dim3 go(1024 / 128, M_TOTAL / 128, 1);
    gemm_hmma2_kernel<<<go, 256, GEMM_SMEM>>>(ahi, alo, whi + 3 * (size_t)NW,
                                              wlo + 3 * (size_t)NW,
                                              out, out, out, freqs, 0);
}